// round 4
// baseline (speedup 1.0000x reference)
#include <cuda_runtime.h>
#include <cuda_fp16.h>
#include <math.h>
#include <cstdint>

// Problem constants
#define D_MODEL 1024
#define SEQ_L   4096
#define BATCH   4
#define M_TOK   (BATCH * SEQ_L)     // 16384 tokens
#define N1      (3 * D_MODEL)       // 3072
#define NSEG    64
#define SEGLEN  (SEQ_L / NSEG)      // 64
#define NSEQ    (BATCH * D_MODEL)   // 4096 scan sequences
#define LN_EPS  1e-5f

// ---------------------------------------------------------------------------
// Scratch (static device arrays, allocation-free)
// ---------------------------------------------------------------------------
__device__ float g_u[(size_t)M_TOK * N1];      // 192 MB: u = x@W_in + b_in
__device__ float g_g[(size_t)M_TOK * D_MODEL]; // 64 MB: scan/gate output
__device__ float g_segA[NSEG * NSEQ];
__device__ float g_segB[NSEG * NSEQ];
__device__ float g_carry[NSEG * NSEQ];

// fp16 operands (A split hi/lo, B plain fp16 transposed [N,K])
__device__ __half g_A1hi[(size_t)M_TOK * D_MODEL];
__device__ __half g_A1lo[(size_t)M_TOK * D_MODEL];
__device__ __half g_B1t [(size_t)N1 * D_MODEL];
__device__ __half g_A2hi[(size_t)M_TOK * D_MODEL];
__device__ __half g_A2lo[(size_t)M_TOK * D_MODEL];
__device__ __half g_B2t [(size_t)D_MODEL * D_MODEL];

// ---------------------------------------------------------------------------
// PTX helpers (base sm_100-legal only: cp.async, ldmatrix, mma.sync)
// ---------------------------------------------------------------------------
__device__ __forceinline__ uint32_t smem_u32(const void* p) {
    uint32_t a;
    asm("{ .reg .u64 t; cvta.to.shared.u64 t, %1; cvt.u32.u64 %0, t; }" : "=r"(a) : "l"(p));
    return a;
}
#define CP16(smem_addr, gptr) \
    asm volatile("cp.async.cg.shared.global [%0], [%1], 16;" :: "r"(smem_addr), "l"(gptr))
#define CP_COMMIT() asm volatile("cp.async.commit_group;" ::: "memory")
#define CP_WAIT1()  asm volatile("cp.async.wait_group 1;" ::: "memory")

#define LDSM4(r0, r1, r2, r3, addr) \
    asm volatile("ldmatrix.sync.aligned.m8n8.x4.shared.b16 {%0,%1,%2,%3}, [%4];" \
                 : "=r"(r0), "=r"(r1), "=r"(r2), "=r"(r3) : "r"(addr))

__device__ __forceinline__ void mma16816(float* c, uint32_t a0, uint32_t a1,
                                         uint32_t a2, uint32_t a3,
                                         uint32_t b0, uint32_t b1) {
    asm volatile(
        "mma.sync.aligned.m16n8k16.row.col.f32.f16.f16.f32 "
        "{%0,%1,%2,%3}, {%4,%5,%6,%7}, {%8,%9}, {%0,%1,%2,%3};"
        : "+f"(c[0]), "+f"(c[1]), "+f"(c[2]), "+f"(c[3])
        : "r"(a0), "r"(a1), "r"(a2), "r"(a3), "r"(b0), "r"(b1));
}

// ---------------------------------------------------------------------------
// fp16 split GEMM: C[M,N] = (Ahi+Alo)[M,K] @ Bt[N,K]^T + bias
// CTA 128x128, BK=32, 256 threads (8 warps of 64x32), cp.async 3-stage.
// SMEM tile stride: 32 halfs padded to 40 (80B) -> conflict-free ldmatrix.
// ---------------------------------------------------------------------------
#define ROW_STRIDE_B 80               // bytes per smem tile row
#define TILE_SM (128 * ROW_STRIDE_B)  // 10240 B per tile
#define STAGE_SM (3 * TILE_SM)        // Ahi, Alo, B = 30720 B
#define STAGES 3
#define GEMM_SMEM (STAGES * STAGE_SM) // 92160 B

__global__ __launch_bounds__(256, 2)
void gemm_fp16split_kernel(const __half* __restrict__ Ahi,
                           const __half* __restrict__ Alo,
                           const __half* __restrict__ Bt,
                           const float* __restrict__ bias,
                           float* __restrict__ C,
                           int M, int N, int K)
{
    extern __shared__ char smem[];
    const uint32_t sbase = smem_u32(smem);
    const int tid = threadIdx.x;
    const int wid = tid >> 5, lane = tid & 31;
    const int blockRow = blockIdx.y * 128;
    const int blockCol = blockIdx.x * 128;
    const int m0 = (wid & 1) * 64;        // warp row origin in tile
    const int n0 = (wid >> 1) * 32;       // warp col origin in tile
    const int NC = K / 32;

    float acc[4][4][4];
    #pragma unroll
    for (int mt = 0; mt < 4; mt++)
        #pragma unroll
        for (int nt = 0; nt < 4; nt++)
            #pragma unroll
            for (int i = 0; i < 4; i++) acc[mt][nt][i] = 0.f;

    // ---- stage loader: 128 rows x 64B per tile = 512 x 16B chunks ----
    auto load_stage = [&](int stage, int k0) {
        const uint32_t st = sbase + stage * STAGE_SM;
        #pragma unroll
        for (int i = 0; i < 2; i++) {
            int cid = tid + i * 256;            // 0..511
            int row = cid >> 2, c = cid & 3;
            uint32_t so = st + row * ROW_STRIDE_B + c * 16;
            size_t ga = (size_t)(blockRow + row) * K + k0 + c * 8;
            CP16(so, Ahi + ga);
            CP16(so + TILE_SM, Alo + ga);
            size_t gb = (size_t)(blockCol + row) * K + k0 + c * 8;
            CP16(so + 2 * TILE_SM, Bt + gb);
        }
    };

    // lane-derived ldmatrix address components
    const uint32_t a_row = (lane & 15);
    const uint32_t a_cb  = (lane >> 4) * 16;              // col byte offset
    const uint32_t b_n   = (lane & 7) | ((lane & 16) >> 1);
    const uint32_t b_kb  = ((lane >> 3) & 1) * 16;        // k byte offset

    load_stage(0, 0);
    CP_COMMIT();
    load_stage(1, 32);
    CP_COMMIT();

    for (int kc = 0; kc < NC; kc++) {
        CP_WAIT1();               // chunk kc resident (kc+1 may be in flight)
        __syncthreads();

        if (kc + 2 < NC) load_stage((kc + 2) % STAGES, (kc + 2) * 32);
        CP_COMMIT();              // empty commits at tail keep group count uniform

        const uint32_t st = sbase + (kc % STAGES) * STAGE_SM;
        #pragma unroll
        for (int k16 = 0; k16 < 2; k16++) {
            uint32_t bf[4][2];
            #pragma unroll
            for (int j = 0; j < 2; j++) {
                uint32_t baddr = st + 2 * TILE_SM
                               + (n0 + j * 16 + b_n) * ROW_STRIDE_B
                               + k16 * 32 + b_kb;
                LDSM4(bf[2 * j][0], bf[2 * j][1], bf[2 * j + 1][0], bf[2 * j + 1][1], baddr);
            }
            #pragma unroll
            for (int mt = 0; mt < 4; mt++) {
                uint32_t aaddr = st + (m0 + mt * 16 + a_row) * ROW_STRIDE_B
                               + k16 * 32 + a_cb;
                uint32_t h0, h1, h2, h3, l0, l1, l2, l3;
                LDSM4(h0, h1, h2, h3, aaddr);
                LDSM4(l0, l1, l2, l3, aaddr + TILE_SM);
                #pragma unroll
                for (int nt = 0; nt < 4; nt++) {
                    mma16816(acc[mt][nt], h0, h1, h2, h3, bf[nt][0], bf[nt][1]);
                    mma16816(acc[mt][nt], l0, l1, l2, l3, bf[nt][0], bf[nt][1]);
                }
            }
        }
        __syncthreads();
    }

    // ---- epilogue: direct global stores ----
    const int g = lane >> 2, t4 = lane & 3;
    #pragma unroll
    for (int mt = 0; mt < 4; mt++) {
        #pragma unroll
        for (int nt = 0; nt < 4; nt++) {
            int col = blockCol + n0 + nt * 8 + 2 * t4;
            float2 b2 = *(const float2*)(bias + col);
            int r0 = blockRow + m0 + mt * 16 + g;
            float2 o0, o1;
            o0.x = acc[mt][nt][0] + b2.x; o0.y = acc[mt][nt][1] + b2.y;
            o1.x = acc[mt][nt][2] + b2.x; o1.y = acc[mt][nt][3] + b2.y;
            *(float2*)(C + (size_t)r0 * N + col) = o0;
            *(float2*)(C + (size_t)(r0 + 8) * N + col) = o1;
        }
    }
}

// ---------------------------------------------------------------------------
// fp32 -> fp16 hi/lo split (elementwise)
// ---------------------------------------------------------------------------
__global__ void split_kernel(const float* __restrict__ src,
                             __half* __restrict__ hi,
                             __half* __restrict__ lo, size_t n4)
{
    size_t i = (size_t)blockIdx.x * blockDim.x + threadIdx.x;
    if (i >= n4) return;
    float4 v = ((const float4*)src)[i];
    __half h0 = __float2half(v.x), h1 = __float2half(v.y);
    __half h2 = __float2half(v.z), h3 = __float2half(v.w);
    __half2* hp = (__half2*)hi + i * 2;
    __half2* lp = (__half2*)lo + i * 2;
    hp[0] = __halves2half2(h0, h1);
    hp[1] = __halves2half2(h2, h3);
    lp[0] = __halves2half2(__float2half(v.x - __half2float(h0)),
                           __float2half(v.y - __half2float(h1)));
    lp[1] = __halves2half2(__float2half(v.z - __half2float(h2)),
                           __float2half(v.w - __half2float(h3)));
}

// ---------------------------------------------------------------------------
// fp32 [R,C] -> transposed fp16 [C,R]
// ---------------------------------------------------------------------------
__global__ void transpose_h_kernel(const float* __restrict__ src,
                                   __half* __restrict__ dst, int R, int C)
{
    __shared__ float tile[32][33];
    int tx = threadIdx.x, ty = threadIdx.y;     // (32, 8)
    int c0 = blockIdx.x * 32, r0 = blockIdx.y * 32;
    #pragma unroll
    for (int j = 0; j < 32; j += 8)
        tile[ty + j][tx] = src[(size_t)(r0 + ty + j) * C + c0 + tx];
    __syncthreads();
    #pragma unroll
    for (int j = 0; j < 32; j += 8)
        dst[(size_t)(c0 + ty + j) * R + r0 + tx] = __float2half(tile[tx][ty + j]);
}

// ---------------------------------------------------------------------------
// Segmented gated scan (3 phases, float4-vectorized over channels)
// ---------------------------------------------------------------------------
__device__ __forceinline__ float4 sigmoid4(float4 x) {
    float4 r;
    r.x = 1.f / (1.f + __expf(-x.x));
    r.y = 1.f / (1.f + __expf(-x.y));
    r.z = 1.f / (1.f + __expf(-x.z));
    r.w = 1.f / (1.f + __expf(-x.w));
    return r;
}

__global__ void scan_phaseA_kernel()
{
    int id = blockIdx.x * blockDim.x + threadIdx.x;   // over B*NSEG*(D/4)
    if (id >= BATCH * NSEG * (D_MODEL / 4)) return;
    int c4  = id % (D_MODEL / 4);
    int seg = (id / (D_MODEL / 4)) % NSEG;
    int b   = id / ((D_MODEL / 4) * NSEG);
    const char* base = (const char*)(g_u + (size_t)(b * SEQ_L + seg * SEGLEN) * N1);
    const size_t stride = (size_t)N1 * 4;             // row stride in bytes
    const int co = c4 * 16;                           // channel byte offset
    float4 A = make_float4(1.f, 1.f, 1.f, 1.f);
    float4 Bc = make_float4(0.f, 0.f, 0.f, 0.f);
    for (int i = 0; i < SEGLEN; i++) {
        float4 fl = *(const float4*)(base + i * stride + 2 * D_MODEL * 4 + co);
        float4 v  = *(const float4*)(base + i * stride + co);
        float4 f  = sigmoid4(fl);
        A.x *= f.x; A.y *= f.y; A.z *= f.z; A.w *= f.w;
        Bc.x = f.x * Bc.x + (1.f - f.x) * v.x;
        Bc.y = f.y * Bc.y + (1.f - f.y) * v.y;
        Bc.z = f.z * Bc.z + (1.f - f.z) * v.z;
        Bc.w = f.w * Bc.w + (1.f - f.w) * v.w;
    }
    int idx = seg * (NSEQ / 4) + b * (D_MODEL / 4) + c4;
    ((float4*)g_segA)[idx] = A;
    ((float4*)g_segB)[idx] = Bc;
}

__global__ void scan_phaseB_kernel()
{
    int id = blockIdx.x * blockDim.x + threadIdx.x;   // 0..NSEQ/4-1
    if (id >= NSEQ / 4) return;
    float4 h = make_float4(0.f, 0.f, 0.f, 0.f);
    #pragma unroll 4
    for (int s = 0; s < NSEG; s++) {
        ((float4*)g_carry)[s * (NSEQ / 4) + id] = h;
        float4 A = ((const float4*)g_segA)[s * (NSEQ / 4) + id];
        float4 Bc = ((const float4*)g_segB)[s * (NSEQ / 4) + id];
        h.x = A.x * h.x + Bc.x;
        h.y = A.y * h.y + Bc.y;
        h.z = A.z * h.z + Bc.z;
        h.w = A.w * h.w + Bc.w;
    }
}

__global__ void scan_phaseC_kernel()
{
    int id = blockIdx.x * blockDim.x + threadIdx.x;
    if (id >= BATCH * NSEG * (D_MODEL / 4)) return;
    int c4  = id % (D_MODEL / 4);
    int seg = (id / (D_MODEL / 4)) % NSEG;
    int b   = id / ((D_MODEL / 4) * NSEG);
    const char* base = (const char*)(g_u + (size_t)(b * SEQ_L + seg * SEGLEN) * N1);
    const size_t stride = (size_t)N1 * 4;
    const int co = c4 * 16;
    char* gout = (char*)(g_g + (size_t)(b * SEQ_L + seg * SEGLEN) * D_MODEL) + c4 * 16;

    float4 h = ((const float4*)g_carry)[seg * (NSEQ / 4) + b * (D_MODEL / 4) + c4];
    for (int i = 0; i < SEGLEN; i++) {
        float4 fl = *(const float4*)(base + i * stride + 2 * D_MODEL * 4 + co);
        float4 v  = *(const float4*)(base + i * stride + co);
        float4 o  = *(const float4*)(base + i * stride + D_MODEL * 4 + co);
        float4 f  = sigmoid4(fl);
        h.x = f.x * h.x + (1.f - f.x) * v.x;
        h.y = f.y * h.y + (1.f - f.y) * v.y;
        h.z = f.z * h.z + (1.f - f.z) * v.z;
        h.w = f.w * h.w + (1.f - f.w) * v.w;
        float4 sg = sigmoid4(o);
        float4 out;
        out.x = h.x * o.x * sg.x;
        out.y = h.y * o.y * sg.y;
        out.z = h.z * o.z * sg.z;
        out.w = h.w * o.w * sg.w;
        *(float4*)(gout + i * (size_t)D_MODEL * 4) = out;
    }
}

// ---------------------------------------------------------------------------
// LayerNorm on g_g -> fp16 hi/lo A2 operands (fused conversion)
// ---------------------------------------------------------------------------
__device__ __forceinline__ float block_reduce_sum_256(float v)
{
    __shared__ float shm[8];
    int lane = threadIdx.x & 31;
    #pragma unroll
    for (int o = 16; o > 0; o >>= 1) v += __shfl_xor_sync(0xffffffffu, v, o);
    __syncthreads();
    if (lane == 0) shm[threadIdx.x >> 5] = v;
    __syncthreads();
    float r = (lane < 8) ? shm[lane] : 0.f;
    #pragma unroll
    for (int o = 4; o > 0; o >>= 1) r += __shfl_xor_sync(0xffffffffu, r, o);
    return __shfl_sync(0xffffffffu, r, 0);
}

__global__ __launch_bounds__(256)
void layernorm_split_kernel(const float* __restrict__ gamma, const float* __restrict__ beta)
{
    const int row = blockIdx.x;
    const float* p = g_g + (size_t)row * D_MODEL;
    const int tid = threadIdx.x;

    float4 v = ((const float4*)p)[tid];
    float s = v.x + v.y + v.z + v.w;
    s = block_reduce_sum_256(s);
    const float mu = s * (1.f / D_MODEL);

    float d0 = v.x - mu, d1 = v.y - mu, d2 = v.z - mu, d3 = v.w - mu;
    float sq = d0 * d0 + d1 * d1 + d2 * d2 + d3 * d3;
    sq = block_reduce_sum_256(sq);
    const float rstd = rsqrtf(sq * (1.f / D_MODEL) + LN_EPS);

    float4 gm = ((const float4*)gamma)[tid];
    float4 bt = ((const float4*)beta)[tid];
    float y0 = d0 * rstd * gm.x + bt.x;
    float y1 = d1 * rstd * gm.y + bt.y;
    float y2 = d2 * rstd * gm.z + bt.z;
    float y3 = d3 * rstd * gm.w + bt.w;

    size_t base = (size_t)row * D_MODEL + tid * 4;
    __half h0 = __float2half(y0), h1 = __float2half(y1);
    __half h2 = __float2half(y2), h3 = __float2half(y3);
    __half2* hp = (__half2*)(g_A2hi + base);
    __half2* lp = (__half2*)(g_A2lo + base);
    hp[0] = __halves2half2(h0, h1);
    hp[1] = __halves2half2(h2, h3);
    lp[0] = __halves2half2(__float2half(y0 - __half2float(h0)),
                           __float2half(y1 - __half2float(h1)));
    lp[1] = __halves2half2(__float2half(y2 - __half2float(h2)),
                           __float2half(y3 - __half2float(h3)));
}

// ---------------------------------------------------------------------------
// Launch
// ---------------------------------------------------------------------------
extern "C" void kernel_launch(void* const* d_in, const int* in_sizes, int n_in,
                              void* d_out, int out_size)
{
    const float* x     = (const float*)d_in[0];
    const float* W_in  = (const float*)d_in[1];
    const float* b_in  = (const float*)d_in[2];
    const float* gamma = (const float*)d_in[3];
    const float* beta  = (const float*)d_in[4];
    const float* W_out = (const float*)d_in[5];
    const float* b_out = (const float*)d_in[6];
    float* out = (float*)d_out;

    float* u_ptr;
    cudaGetSymbolAddress((void**)&u_ptr, g_u);
    __half *a1h, *a1l, *b1t, *a2h, *a2l, *b2t;
    cudaGetSymbolAddress((void**)&a1h, g_A1hi);
    cudaGetSymbolAddress((void**)&a1l, g_A1lo);
    cudaGetSymbolAddress((void**)&b1t, g_B1t);
    cudaGetSymbolAddress((void**)&a2h, g_A2hi);
    cudaGetSymbolAddress((void**)&a2l, g_A2lo);
    cudaGetSymbolAddress((void**)&b2t, g_B2t);

    cudaFuncSetAttribute(gemm_fp16split_kernel,
                         cudaFuncAttributeMaxDynamicSharedMemorySize, GEMM_SMEM);

    // 0) operand conversion
    {
        size_t n4 = (size_t)M_TOK * D_MODEL / 4;
        split_kernel<<<(unsigned)((n4 + 255) / 256), 256>>>(x, a1h, a1l, n4);
        dim3 blk(32, 8);
        transpose_h_kernel<<<dim3(N1 / 32, D_MODEL / 32), blk>>>(W_in, b1t, D_MODEL, N1);
        transpose_h_kernel<<<dim3(D_MODEL / 32, D_MODEL / 32), blk>>>(W_out, b2t, D_MODEL, D_MODEL);
    }

    // 1) u = x @ W_in + b_in   [16384, 3072]
    gemm_fp16split_kernel<<<dim3(N1 / 128, M_TOK / 128), 256, GEMM_SMEM>>>(
        a1h, a1l, b1t, b_in, u_ptr, M_TOK, N1, D_MODEL);

    // 2-4) segmented gated scan (float4 over channels)
    {
        int total = BATCH * NSEG * (D_MODEL / 4);      // 65536
        scan_phaseA_kernel<<<total / 256, 256>>>();
        scan_phaseB_kernel<<<(NSEQ / 4) / 256, 256>>>();
        scan_phaseC_kernel<<<total / 256, 256>>>();
    }

    // 5) LayerNorm -> A2 fp16 hi/lo
    layernorm_split_kernel<<<M_TOK, 256>>>(gamma, beta);

    // 6) out = y @ W_out + b_out  [16384, 1024]
    gemm_fp16split_kernel<<<dim3(D_MODEL / 128, M_TOK / 128), 256, GEMM_SMEM>>>(
        a2h, a2l, b2t, b_out, out, M_TOK, D_MODEL, D_MODEL);
}

// round 5
// speedup vs baseline: 1.6121x; 1.6121x over previous
#include <cuda_runtime.h>
#include <cuda_fp16.h>
#include <math.h>
#include <cstdint>

// Problem constants
#define D_MODEL 1024
#define SEQ_L   4096
#define BATCH   4
#define M_TOK   (BATCH * SEQ_L)     // 16384 tokens
#define N1      (3 * D_MODEL)       // 3072
#define NSEG    64
#define SEGLEN  (SEQ_L / NSEG)      // 64
#define NSEQ    (BATCH * D_MODEL)   // 4096 scan sequences
#define LN_EPS  1e-5f

// ---------------------------------------------------------------------------
// Scratch (static device arrays, allocation-free)
// ---------------------------------------------------------------------------
__device__ float g_u[(size_t)M_TOK * N1];      // 192 MB: u = x@W_in + b_in
__device__ float g_g[(size_t)M_TOK * D_MODEL]; // 64 MB: scan/gate output
__device__ float g_segA[NSEG * NSEQ];
__device__ float g_segB[NSEG * NSEQ];
__device__ float g_carry[NSEG * NSEQ];

// fp16 operands (plain fp16 A, B transposed [N,K])
__device__ __half g_A1[(size_t)M_TOK * D_MODEL];
__device__ __half g_B1t[(size_t)N1 * D_MODEL];
__device__ __half g_A2[(size_t)M_TOK * D_MODEL];
__device__ __half g_B2t[(size_t)D_MODEL * D_MODEL];

// ---------------------------------------------------------------------------
// PTX helpers (base sm_100-legal: cp.async, ldmatrix, mma.sync)
// ---------------------------------------------------------------------------
__device__ __forceinline__ uint32_t smem_u32(const void* p) {
    uint32_t a;
    asm("{ .reg .u64 t; cvta.to.shared.u64 t, %1; cvt.u32.u64 %0, t; }" : "=r"(a) : "l"(p));
    return a;
}
#define CP16(smem_addr, gptr) \
    asm volatile("cp.async.cg.shared.global [%0], [%1], 16;" :: "r"(smem_addr), "l"(gptr))
#define CP_COMMIT() asm volatile("cp.async.commit_group;" ::: "memory")
#define CP_WAIT2()  asm volatile("cp.async.wait_group 2;" ::: "memory")

#define LDSM4(r0, r1, r2, r3, addr) \
    asm volatile("ldmatrix.sync.aligned.m8n8.x4.shared.b16 {%0,%1,%2,%3}, [%4];" \
                 : "=r"(r0), "=r"(r1), "=r"(r2), "=r"(r3) : "r"(addr))

__device__ __forceinline__ void mma16816(float* c, uint32_t a0, uint32_t a1,
                                         uint32_t a2, uint32_t a3,
                                         uint32_t b0, uint32_t b1) {
    asm volatile(
        "mma.sync.aligned.m16n8k16.row.col.f32.f16.f16.f32 "
        "{%0,%1,%2,%3}, {%4,%5,%6,%7}, {%8,%9}, {%0,%1,%2,%3};"
        : "+f"(c[0]), "+f"(c[1]), "+f"(c[2]), "+f"(c[3])
        : "r"(a0), "r"(a1), "r"(a2), "r"(a3), "r"(b0), "r"(b1));
}

// ---------------------------------------------------------------------------
// fp16 GEMM: C[M,N] = A[M,K] @ Bt[N,K]^T + bias
// CTA 128x128, BK=32, 256 threads (8 warps of 64x32), cp.async 4-stage.
// SMEM tile stride: 32 halfs padded to 40 (80B) -> conflict-free ldmatrix.
// ---------------------------------------------------------------------------
#define ROW_STRIDE_B 80               // bytes per smem tile row
#define TILE_SM (128 * ROW_STRIDE_B)  // 10240 B per tile
#define STAGE_SM (2 * TILE_SM)        // A, B = 20480 B
#define STAGES 4
#define GEMM_SMEM (STAGES * STAGE_SM) // 81920 B

__global__ __launch_bounds__(256, 2)
void gemm_fp16_kernel(const __half* __restrict__ A,
                      const __half* __restrict__ Bt,
                      const float* __restrict__ bias,
                      float* __restrict__ C,
                      int M, int N, int K)
{
    extern __shared__ char smem[];
    const uint32_t sbase = smem_u32(smem);
    const int tid = threadIdx.x;
    const int wid = tid >> 5, lane = tid & 31;
    const int blockRow = blockIdx.y * 128;
    const int blockCol = blockIdx.x * 128;
    const int m0 = (wid & 1) * 64;        // warp row origin in tile
    const int n0 = (wid >> 1) * 32;       // warp col origin in tile
    const int NC = K / 32;

    float acc[4][4][4];
    #pragma unroll
    for (int mt = 0; mt < 4; mt++)
        #pragma unroll
        for (int nt = 0; nt < 4; nt++)
            #pragma unroll
            for (int i = 0; i < 4; i++) acc[mt][nt][i] = 0.f;

    // ---- stage loader: 2 tiles x 128 rows x 64B = 1024 x 16B chunks ----
    auto load_stage = [&](int stage, int k0) {
        const uint32_t st = sbase + stage * STAGE_SM;
        #pragma unroll
        for (int i = 0; i < 2; i++) {
            int cid = tid + i * 256;            // 0..511
            int row = cid >> 2, c = cid & 3;
            uint32_t so = st + row * ROW_STRIDE_B + c * 16;
            size_t ga = (size_t)(blockRow + row) * K + k0 + c * 8;
            CP16(so, A + ga);
            size_t gb = (size_t)(blockCol + row) * K + k0 + c * 8;
            CP16(so + TILE_SM, Bt + gb);
        }
    };

    // lane-derived ldmatrix address components
    const uint32_t a_row = (lane & 15);
    const uint32_t a_cb  = (lane >> 4) * 16;              // col byte offset
    const uint32_t b_n   = (lane & 7) | ((lane & 16) >> 1);
    const uint32_t b_kb  = ((lane >> 3) & 1) * 16;        // k byte offset

    load_stage(0, 0);  CP_COMMIT();
    load_stage(1, 32); CP_COMMIT();
    load_stage(2, 64); CP_COMMIT();

    for (int kc = 0; kc < NC; kc++) {
        CP_WAIT2();               // chunk kc resident; kc+1, kc+2 may be in flight
        __syncthreads();

        if (kc + 3 < NC) load_stage((kc + 3) % STAGES, (kc + 3) * 32);
        CP_COMMIT();              // empty commits at tail keep group count uniform

        const uint32_t st = sbase + (kc % STAGES) * STAGE_SM;
        #pragma unroll
        for (int k16 = 0; k16 < 2; k16++) {
            uint32_t bf[4][2];
            #pragma unroll
            for (int j = 0; j < 2; j++) {
                uint32_t baddr = st + TILE_SM
                               + (n0 + j * 16 + b_n) * ROW_STRIDE_B
                               + k16 * 32 + b_kb;
                LDSM4(bf[2 * j][0], bf[2 * j][1], bf[2 * j + 1][0], bf[2 * j + 1][1], baddr);
            }
            #pragma unroll
            for (int mt = 0; mt < 4; mt++) {
                uint32_t aaddr = st + (m0 + mt * 16 + a_row) * ROW_STRIDE_B
                               + k16 * 32 + a_cb;
                uint32_t a0, a1, a2, a3;
                LDSM4(a0, a1, a2, a3, aaddr);
                #pragma unroll
                for (int nt = 0; nt < 4; nt++)
                    mma16816(acc[mt][nt], a0, a1, a2, a3, bf[nt][0], bf[nt][1]);
            }
        }
        __syncthreads();
    }

    // ---- epilogue: direct global stores ----
    const int g = lane >> 2, t4 = lane & 3;
    #pragma unroll
    for (int mt = 0; mt < 4; mt++) {
        #pragma unroll
        for (int nt = 0; nt < 4; nt++) {
            int col = blockCol + n0 + nt * 8 + 2 * t4;
            float2 b2 = *(const float2*)(bias + col);
            int r0 = blockRow + m0 + mt * 16 + g;
            float2 o0, o1;
            o0.x = acc[mt][nt][0] + b2.x; o0.y = acc[mt][nt][1] + b2.y;
            o1.x = acc[mt][nt][2] + b2.x; o1.y = acc[mt][nt][3] + b2.y;
            *(float2*)(C + (size_t)r0 * N + col) = o0;
            *(float2*)(C + (size_t)(r0 + 8) * N + col) = o1;
        }
    }
}

// ---------------------------------------------------------------------------
// fp32 -> fp16 convert (elementwise)
// ---------------------------------------------------------------------------
__global__ void convert_kernel(const float* __restrict__ src,
                               __half* __restrict__ dst, size_t n4)
{
    size_t i = (size_t)blockIdx.x * blockDim.x + threadIdx.x;
    if (i >= n4) return;
    float4 v = ((const float4*)src)[i];
    __half2* dp = (__half2*)dst + i * 2;
    dp[0] = __halves2half2(__float2half(v.x), __float2half(v.y));
    dp[1] = __halves2half2(__float2half(v.z), __float2half(v.w));
}

// ---------------------------------------------------------------------------
// fp32 [R,C] -> transposed fp16 [C,R]
// ---------------------------------------------------------------------------
__global__ void transpose_h_kernel(const float* __restrict__ src,
                                   __half* __restrict__ dst, int R, int C)
{
    __shared__ float tile[32][33];
    int tx = threadIdx.x, ty = threadIdx.y;     // (32, 8)
    int c0 = blockIdx.x * 32, r0 = blockIdx.y * 32;
    #pragma unroll
    for (int j = 0; j < 32; j += 8)
        tile[ty + j][tx] = src[(size_t)(r0 + ty + j) * C + c0 + tx];
    __syncthreads();
    #pragma unroll
    for (int j = 0; j < 32; j += 8)
        dst[(size_t)(c0 + ty + j) * R + r0 + tx] = __float2half(tile[tx][ty + j]);
}

// ---------------------------------------------------------------------------
// Segmented gated scan (3 phases, scalar — fastest measured variant)
// ---------------------------------------------------------------------------
__global__ void scan_phaseA_kernel()
{
    int id = blockIdx.x * blockDim.x + threadIdx.x;
    if (id >= BATCH * NSEG * D_MODEL) return;
    int c = id % D_MODEL;
    int seg = (id / D_MODEL) % NSEG;
    int b = id / (D_MODEL * NSEG);
    const float* base = g_u + (size_t)(b * SEQ_L + seg * SEGLEN) * N1;
    float A = 1.f, Bc = 0.f;
    for (int i = 0; i < SEGLEN; i++) {
        float fl = base[(size_t)i * N1 + 2 * D_MODEL + c];
        float v = base[(size_t)i * N1 + c];
        float f = 1.f / (1.f + __expf(-fl));
        A = f * A;
        Bc = f * Bc + (1.f - f) * v;
    }
    int idx = seg * NSEQ + b * D_MODEL + c;
    g_segA[idx] = A;
    g_segB[idx] = Bc;
}

__global__ void scan_phaseB_kernel()
{
    int id = blockIdx.x * blockDim.x + threadIdx.x;
    if (id >= NSEQ) return;
    float h = 0.f;
    #pragma unroll 8
    for (int s = 0; s < NSEG; s++) {
        g_carry[s * NSEQ + id] = h;
        h = g_segA[s * NSEQ + id] * h + g_segB[s * NSEQ + id];
    }
}

__global__ void scan_phaseC_kernel()
{
    int id = blockIdx.x * blockDim.x + threadIdx.x;
    if (id >= BATCH * NSEG * D_MODEL) return;
    int c = id % D_MODEL;
    int seg = (id / D_MODEL) % NSEG;
    int b = id / (D_MODEL * NSEG);
    const float* base = g_u + (size_t)(b * SEQ_L + seg * SEGLEN) * N1;
    float* gout = g_g + (size_t)(b * SEQ_L + seg * SEGLEN) * D_MODEL + c;
    float h = g_carry[seg * NSEQ + b * D_MODEL + c];
    for (int i = 0; i < SEGLEN; i++) {
        float fl = base[(size_t)i * N1 + 2 * D_MODEL + c];
        float v = base[(size_t)i * N1 + c];
        float o = base[(size_t)i * N1 + D_MODEL + c];
        float f = 1.f / (1.f + __expf(-fl));
        h = f * h + (1.f - f) * v;
        float silu = o / (1.f + __expf(-o));
        gout[(size_t)i * D_MODEL] = h * silu;
    }
}

// ---------------------------------------------------------------------------
// LayerNorm on g_g -> fp16 A2 operand (fused conversion)
// ---------------------------------------------------------------------------
__device__ __forceinline__ float block_reduce_sum_256(float v)
{
    __shared__ float shm[8];
    int lane = threadIdx.x & 31;
    #pragma unroll
    for (int o = 16; o > 0; o >>= 1) v += __shfl_xor_sync(0xffffffffu, v, o);
    __syncthreads();
    if (lane == 0) shm[threadIdx.x >> 5] = v;
    __syncthreads();
    float r = (lane < 8) ? shm[lane] : 0.f;
    #pragma unroll
    for (int o = 4; o > 0; o >>= 1) r += __shfl_xor_sync(0xffffffffu, r, o);
    return __shfl_sync(0xffffffffu, r, 0);
}

__global__ __launch_bounds__(256)
void layernorm_h_kernel(const float* __restrict__ gamma, const float* __restrict__ beta)
{
    const int row = blockIdx.x;
    const float* p = g_g + (size_t)row * D_MODEL;
    const int tid = threadIdx.x;

    float4 v = ((const float4*)p)[tid];
    float s = v.x + v.y + v.z + v.w;
    s = block_reduce_sum_256(s);
    const float mu = s * (1.f / D_MODEL);

    float d0 = v.x - mu, d1 = v.y - mu, d2 = v.z - mu, d3 = v.w - mu;
    float sq = d0 * d0 + d1 * d1 + d2 * d2 + d3 * d3;
    sq = block_reduce_sum_256(sq);
    const float rstd = rsqrtf(sq * (1.f / D_MODEL) + LN_EPS);

    float4 gm = ((const float4*)gamma)[tid];
    float4 bt = ((const float4*)beta)[tid];
    float y0 = d0 * rstd * gm.x + bt.x;
    float y1 = d1 * rstd * gm.y + bt.y;
    float y2 = d2 * rstd * gm.z + bt.z;
    float y3 = d3 * rstd * gm.w + bt.w;

    size_t base = (size_t)row * D_MODEL + tid * 4;
    __half2* hp = (__half2*)(g_A2 + base);
    hp[0] = __halves2half2(__float2half(y0), __float2half(y1));
    hp[1] = __halves2half2(__float2half(y2), __float2half(y3));
}

// ---------------------------------------------------------------------------
// Launch
// ---------------------------------------------------------------------------
extern "C" void kernel_launch(void* const* d_in, const int* in_sizes, int n_in,
                              void* d_out, int out_size)
{
    const float* x     = (const float*)d_in[0];
    const float* W_in  = (const float*)d_in[1];
    const float* b_in  = (const float*)d_in[2];
    const float* gamma = (const float*)d_in[3];
    const float* beta  = (const float*)d_in[4];
    const float* W_out = (const float*)d_in[5];
    const float* b_out = (const float*)d_in[6];
    float* out = (float*)d_out;

    float* u_ptr;
    cudaGetSymbolAddress((void**)&u_ptr, g_u);
    __half *a1, *b1t, *a2, *b2t;
    cudaGetSymbolAddress((void**)&a1, g_A1);
    cudaGetSymbolAddress((void**)&b1t, g_B1t);
    cudaGetSymbolAddress((void**)&a2, g_A2);
    cudaGetSymbolAddress((void**)&b2t, g_B2t);

    cudaFuncSetAttribute(gemm_fp16_kernel,
                         cudaFuncAttributeMaxDynamicSharedMemorySize, GEMM_SMEM);

    // 0) operand conversion
    {
        size_t n4 = (size_t)M_TOK * D_MODEL / 4;
        convert_kernel<<<(unsigned)((n4 + 255) / 256), 256>>>(x, a1, n4);
        dim3 blk(32, 8);
        transpose_h_kernel<<<dim3(N1 / 32, D_MODEL / 32), blk>>>(W_in, b1t, D_MODEL, N1);
        transpose_h_kernel<<<dim3(D_MODEL / 32, D_MODEL / 32), blk>>>(W_out, b2t, D_MODEL, D_MODEL);
    }

    // 1) u = x @ W_in + b_in   [16384, 3072]
    gemm_fp16_kernel<<<dim3(N1 / 128, M_TOK / 128), 256, GEMM_SMEM>>>(
        a1, b1t, b_in, u_ptr, M_TOK, N1, D_MODEL);

    // 2-4) segmented gated scan
    {
        int total = BATCH * NSEG * D_MODEL;
        scan_phaseA_kernel<<<total / 256, 256>>>();
        scan_phaseB_kernel<<<NSEQ / 256, 256>>>();
        scan_phaseC_kernel<<<total / 256, 256>>>();
    }

    // 5) LayerNorm -> A2 fp16
    layernorm_h_kernel<<<M_TOK, 256>>>(gamma, beta);

    // 6) out = y @ W_out + b_out  [16384, 1024]
    gemm_fp16_kernel<<<dim3(D_MODEL / 128, M_TOK / 128), 256, GEMM_SMEM>>>(
        a2, b2t, b_out, out, M_TOK, D_MODEL, D_MODEL);
}